// round 3
// baseline (speedup 1.0000x reference)
#include <cuda_runtime.h>
#include <cstdint>

#define NB_B 8192
#define LOD 60
#define LSD 120
#define AD 10
#define NB 15
#define HH 60

typedef unsigned long long u64;

// ---- device scratch ----
__device__ float4 g_tmb[LOD * 7 * NB];     // (t11,t21,t12,t22) banded
__device__ float  g_coef[NB * NB_B];       // softmax coefs, [k][b]
__device__ float  g_ctl[LSD * NB_B];       // control, [c][b]
__device__ float  g_tc[LSD];               // elup1(log_noise)

// ---- f32x2 helpers ----
#define FMA2(acc, a, b) asm("fma.rn.f32x2 %0, %1, %2, %0;" : "+l"(acc) : "l"(a), "l"(b))
__device__ __forceinline__ u64 MUL2(u64 a, u64 b){ u64 d; asm("mul.rn.f32x2 %0,%1,%2;" : "=l"(d) : "l"(a), "l"(b)); return d; }
__device__ __forceinline__ u64 ADD2(u64 a, u64 b){ u64 d; asm("add.rn.f32x2 %0,%1,%2;" : "=l"(d) : "l"(a), "l"(b)); return d; }
__device__ __forceinline__ float2 U2F(u64 v){ float2 r; asm("mov.b64 {%0,%1},%2;" : "=f"(r.x), "=f"(r.y) : "l"(v)); return r; }
__device__ __forceinline__ u64 F2U(float x, float y){ u64 r; asm("mov.b64 %0,{%1,%2};" : "=l"(r) : "f"(x), "f"(y)); return r; }
__device__ __forceinline__ u64 LDS64(uint32_t a){ u64 r; asm("ld.shared.b64 %0,[%1];" : "=l"(r) : "r"(a)); return r; }

// ======================= prep kernel =======================
// blocks 0..127: coef softmax + control MLP, 64 batch each, block (64,8)
// blocks 128..140: tmb pack (+ tc on 128)
#define PP_PM  0        // 120*66
#define PP_LG  7920     // 15*66
#define PP_ACT 8910     // 10*66
#define PP_H   9570     // 60*66
#define PP_WC  13530    // 1800
#define PP_W1  15330    // 600
#define PP_W2  15930    // 7200
#define PP_B1  23130
#define PP_B2  23190
#define PP_BC  23310
#define PP_SMEM 23328

__global__ void __launch_bounds__(512) prep_kernel(
    const float* __restrict__ post_mean, const float* __restrict__ action,
    const float* __restrict__ tm11, const float* __restrict__ tm12,
    const float* __restrict__ tm21, const float* __restrict__ tm22,
    const float* __restrict__ log_noise,
    const float* __restrict__ w_coef, const float* __restrict__ b_coef,
    const float* __restrict__ w_c1, const float* __restrict__ b_c1,
    const float* __restrict__ w_c2, const float* __restrict__ b_c2)
{
    const int bid = blockIdx.x;
    const int bl = threadIdx.x;          // 0..63
    const int yy = threadIdx.y;          // 0..7
    const int tid = yy * 64 + bl;

    if (bid >= 128) {
        if (bid == 128 && tid < LSD) {
            float x = log_noise[tid];
            g_tc[tid] = (x < 0.f) ? expf(x) : x + 1.f;
        }
        int idx = (bid - 128) * 512 + tid;
        if (idx < LOD * 7 * NB) {
            int k = idx % NB;
            int jj = (idx / NB) % 7;
            int i = idx / (NB * 7);
            int j = i + jj - 3;
            float4 v = make_float4(0.f, 0.f, 0.f, 0.f);
            if (j >= 0 && j < LOD) {
                int off = k * LOD * LOD + i * LOD + j;
                v.x = tm11[off]; v.y = tm21[off];
                v.z = tm12[off]; v.w = tm22[off];
            }
            g_tmb[idx] = v;
        }
        return;
    }

    extern __shared__ float sp[];
    const int b0 = bid * 64;

    for (int e = tid; e < 64 * LSD; e += 512) {
        int b = e / LSD, d = e % LSD;
        sp[PP_PM + d * 66 + b] = post_mean[(b0 + b) * LSD + d];
    }
    for (int e = tid; e < 64 * AD; e += 512) {
        int b = e / AD, d = e % AD;
        sp[PP_ACT + d * 66 + b] = action[(b0 + b) * AD + d];
    }
    for (int e = tid; e < NB * LSD; e += 512) sp[PP_WC + e] = w_coef[e];
    for (int e = tid; e < HH * AD; e += 512)  sp[PP_W1 + e] = w_c1[e];
    for (int e = tid; e < LSD * HH; e += 512) sp[PP_W2 + e] = w_c2[e];
    if (tid < HH)  sp[PP_B1 + tid] = b_c1[tid];
    if (tid < LSD) sp[PP_B2 + tid] = b_c2[tid];
    if (tid < NB)  sp[PP_BC + tid] = b_coef[tid];
    __syncthreads();

    // logits
    #pragma unroll
    for (int t = 0; t < 2; t++) {
        int k = yy + 8 * t;
        if (k < NB) {
            float lg = sp[PP_BC + k];
            #pragma unroll 4
            for (int d = 0; d < LSD; d++)
                lg = fmaf(sp[PP_WC + k * LSD + d], sp[PP_PM + d * 66 + bl], lg);
            sp[PP_LG + k * 66 + bl] = lg;
        }
    }
    // hidden layer
    #pragma unroll
    for (int t = 0; t < 8; t++) {
        int i = yy + 8 * t;
        if (i < HH) {
            float hv = sp[PP_B1 + i];
            #pragma unroll
            for (int d = 0; d < AD; d++)
                hv = fmaf(sp[PP_W1 + i * AD + d], sp[PP_ACT + d * 66 + bl], hv);
            sp[PP_H + i * 66 + bl] = fmaxf(hv, 0.f);
        }
    }
    __syncthreads();

    // softmax per batch (yy==0 threads cover all 64 bl)
    if (yy == 0) {
        float mx = -1e30f;
        #pragma unroll
        for (int k = 0; k < NB; k++) mx = fmaxf(mx, sp[PP_LG + k * 66 + bl]);
        float ex[NB], sum = 0.f;
        #pragma unroll
        for (int k = 0; k < NB; k++) {
            ex[k] = expf(sp[PP_LG + k * 66 + bl] - mx);
            sum += ex[k];
        }
        float inv = 1.f / sum;
        #pragma unroll
        for (int k = 0; k < NB; k++)
            g_coef[k * NB_B + b0 + bl] = ex[k] * inv;
    }
    // control output
    #pragma unroll
    for (int t = 0; t < 15; t++) {
        int c = yy + 8 * t;
        if (c < LSD) {
            float ctl = sp[PP_B2 + c];
            #pragma unroll 4
            for (int m = 0; m < HH; m++)
                ctl = fmaf(sp[PP_W2 + c * HH + m], sp[PP_H + m * 66 + bl], ctl);
            g_ctl[c * NB_B + b0 + bl] = ctl;
        }
    }
}

// ======================= main kernel =======================
// smem float offsets
#define SM_TMB   0        // 25200  (also stage0 @0..9900, stage1 @12600..22500)
#define SM_MU    25200    // 60*66
#define SM_ML    29160
#define SM_CU    33120
#define SM_CL    37080
#define SM_CS2   41040
#define SM_COEF4 45000    // float4[15][32] = 1920 floats
#define SM_TC    46920    // 120
#define SM_FLOATS 47040

template<int J0, int JN>
__device__ __forceinline__ void mix_pass(
    uint32_t tmb_row, uint32_t coef_base,
    u64* aXA, u64* aXB, u64* aYA, u64* aYB)
{
    #pragma unroll
    for (int jj = 0; jj < JN; jj++) { aXA[jj] = 0; aXB[jj] = 0; aYA[jj] = 0; aYB[jj] = 0; }
    #pragma unroll
    for (int k = 0; k < NB; k++) {
        u64 cA2, cB2;
        asm("ld.shared.v2.u64 {%0,%1},[%2];"
            : "=l"(cA2), "=l"(cB2) : "r"(coef_base + (uint32_t)(k * 512)));
        #pragma unroll
        for (int jj = 0; jj < JN; jj++) {
            u64 v01, v23;   // (t11,t21), (t12,t22)
            asm("ld.shared.v2.u64 {%0,%1},[%2];"
                : "=l"(v01), "=l"(v23)
                : "r"(tmb_row + (uint32_t)(((J0 + jj) * NB + k) * 16)));
            FMA2(aXA[jj], cA2, v01);
            FMA2(aYA[jj], cA2, v23);
            FMA2(aXB[jj], cB2, v01);
            FMA2(aYB[jj], cB2, v23);
        }
    }
}

__device__ __forceinline__ void combine(
    u64 aXA, u64 aXB, u64 aYA, u64 aYB, uint32_t a,
    u64& NMU, u64& NML, u64& NCU, u64& NCL, u64& NCS)
{
    const u64 HALF2 = 0x3f0000003f000000ULL;
    float2 xa = U2F(aXA), xb = U2F(aXB), ya = U2F(aYA), yb = U2F(aYB);
    u64 T11 = F2U(xa.x, xb.x), T21 = F2U(xa.y, xb.y);
    u64 T12 = F2U(ya.x, yb.x), T22 = F2U(ya.y, yb.y);
    u64 MU  = LDS64(a);
    u64 ML  = LDS64(a + 15840u);
    u64 CU  = LDS64(a + 31680u);
    u64 CL  = LDS64(a + 47520u);
    u64 CS2 = LDS64(a + 63360u);
    FMA2(NMU, T11, MU); FMA2(NMU, T12, ML);
    FMA2(NML, T21, MU); FMA2(NML, T22, ML);
    u64 t;
    t = MUL2(T11, T11); FMA2(NCU, t, CU);
    t = MUL2(T11, T12); FMA2(NCU, t, CS2);
    t = MUL2(T12, T12); FMA2(NCU, t, CL);
    t = MUL2(T21, T21); FMA2(NCL, t, CU);
    t = MUL2(T21, T22); FMA2(NCL, t, CS2);
    t = MUL2(T22, T22); FMA2(NCL, t, CL);
    u64 CS = MUL2(CS2, HALF2);
    t = MUL2(T21, T11); FMA2(NCS, t, CU);
    u64 q1 = MUL2(T22, T11);
    u64 q2 = MUL2(T21, T12);
    q1 = ADD2(q1, q2);  FMA2(NCS, q1, CS);
    t = MUL2(T22, T12); FMA2(NCS, t, CL);
}

__global__ void __launch_bounds__(960, 1) acpredict_kernel(
    const float* __restrict__ post_mean, const float* __restrict__ cu_g,
    const float* __restrict__ cl_g, const float* __restrict__ cs_g,
    float* __restrict__ out)
{
    extern __shared__ float sm[];
    const int lane = threadIdx.x;          // 0..31 : batch pair
    const int y    = threadIdx.y;          // 0..29 : row group
    const int tid  = y * 32 + lane;
    const int b0   = blockIdx.x * 64;

    // ---- loads ----
    {
        float4* t4 = (float4*)sm;
        for (int e = tid; e < LOD * 7 * NB; e += 960) t4[e] = g_tmb[e];
    }
    for (int e = tid; e < 64 * LSD; e += 960) {
        int bl = e / LSD, d = e % LSD;
        float v = post_mean[(b0 + bl) * LSD + d];
        if (d < LOD) sm[SM_MU + d * 66 + bl] = v;
        else         sm[SM_ML + (d - LOD) * 66 + bl] = v;
    }
    for (int e = tid; e < 64 * LOD; e += 960) {
        int bl = e / LOD, j = e % LOD;
        sm[SM_CU  + j * 66 + bl] = cu_g[(b0 + bl) * LOD + j];
        sm[SM_CL  + j * 66 + bl] = cl_g[(b0 + bl) * LOD + j];
        sm[SM_CS2 + j * 66 + bl] = 2.f * cs_g[(b0 + bl) * LOD + j];
    }
    if (tid < NB * 32) {
        int k = tid >> 5, l = tid & 31;
        float2 c = *(const float2*)(g_coef + k * NB_B + b0 + 2 * l);
        ((float4*)(sm + SM_COEF4))[k * 32 + l] = make_float4(c.x, c.x, c.y, c.y);
    }
    if (tid < LSD) sm[SM_TC + tid] = g_tc[tid];
    __syncthreads();

    const uint32_t sbase = (uint32_t)__cvta_generic_to_shared(sm);
    const uint32_t coefA = sbase + SM_COEF4 * 4 + (uint32_t)lane * 16u;
    const uint32_t inA   = sbase + SM_MU * 4 + (uint32_t)lane * 8u;
    const u64 ONE_X = 0x000000003f800000ULL;   // +1 on t11 (lo of X)
    const u64 ONE_Y = 0x3f80000000000000ULL;   // +1 on t22 (hi of Y)

    #pragma unroll
    for (int r = 0; r < 2; r++) {
        const int i = y + 30 * r;
        const uint32_t tmbRow = sbase + (uint32_t)(i * 7 * NB * 16);
        u64 NMU = 0, NML = 0, NCU = 0, NCL = 0, NCS = 0;

        {   // pass A: jj 0..3
            u64 aXA[4], aXB[4], aYA[4], aYB[4];
            mix_pass<0, 4>(tmbRow, coefA, aXA, aXB, aYA, aYB);
            #pragma unroll
            for (int jj = 0; jj < 4; jj++) {
                if (jj == 3) {
                    aXA[3] = ADD2(aXA[3], ONE_X); aXB[3] = ADD2(aXB[3], ONE_X);
                    aYA[3] = ADD2(aYA[3], ONE_Y); aYB[3] = ADD2(aYB[3], ONE_Y);
                }
                int jc = max(i + jj - 3, 0);
                combine(aXA[jj], aXB[jj], aYA[jj], aYB[jj],
                        inA + (uint32_t)(jc * 264), NMU, NML, NCU, NCL, NCS);
            }
        }
        {   // pass B: jj 4..6
            u64 aXA[3], aXB[3], aYA[3], aYB[3];
            mix_pass<4, 3>(tmbRow, coefA, aXA, aXB, aYA, aYB);
            #pragma unroll
            for (int jj = 0; jj < 3; jj++) {
                int jc = min(i + jj + 1, LOD - 1);
                combine(aXA[jj], aXB[jj], aYA[jj], aYB[jj],
                        inA + (uint32_t)(jc * 264), NMU, NML, NCU, NCL, NCS);
            }
        }

        // epilogue: control + noise
        float2 ctlu = *(const float2*)(g_ctl + i * NB_B + b0 + 2 * lane);
        float2 ctll = *(const float2*)(g_ctl + (LOD + i) * NB_B + b0 + 2 * lane);
        float2 vn = U2F(NMU); vn.x += ctlu.x; vn.y += ctlu.y;
        float2 vm = U2F(NML); vm.x += ctll.x; vm.y += ctll.y;
        float tci = sm[SM_TC + i], tcl = sm[SM_TC + LOD + i];
        float2 vcu = U2F(NCU); vcu.x += tci; vcu.y += tci;
        float2 vcl = U2F(NCL); vcl.x += tcl; vcl.y += tcl;
        float2 vcs = U2F(NCS);

        __syncthreads();                       // row-r tmb reads complete everywhere
        float* stg = sm + (r ? 12600 : 0);     // stage into dead tmb half
        int po = y * 66 + 2 * lane;
        *(float2*)(stg + po)            = vn;
        *(float2*)(stg + 30 * 66 + po)  = vm;
        *(float2*)(stg + 60 * 66 + po)  = vcu;
        *(float2*)(stg + 90 * 66 + po)  = vcl;
        *(float2*)(stg + 120 * 66 + po) = vcs;
    }
    __syncthreads();

    // ---- coalesced global stores ----
    for (int e = tid; e < 64 * 300; e += 960) {
        int bl = e / 300, c = e % 300;
        int q = c / 60, i2 = c % 60;
        float v = sm[(i2 < 30 ? (q * 30 + i2) * 66
                              : 12600 + (q * 30 + i2 - 30) * 66) + bl];
        int bb = b0 + bl;
        if (c < 120) out[bb * 120 + c] = v;
        else out[NB_B * 120 + (q - 2) * NB_B * 60 + bb * 60 + i2] = v;
    }
}

extern "C" void kernel_launch(void* const* d_in, const int* in_sizes, int n_in,
                              void* d_out, int out_size) {
    const float* post_mean = (const float*)d_in[0];
    const float* cu        = (const float*)d_in[1];
    const float* cl        = (const float*)d_in[2];
    const float* cs        = (const float*)d_in[3];
    const float* action    = (const float*)d_in[4];
    const float* tm11      = (const float*)d_in[5];
    const float* tm12      = (const float*)d_in[6];
    const float* tm21      = (const float*)d_in[7];
    const float* tm22      = (const float*)d_in[8];
    const float* log_noise = (const float*)d_in[9];
    const float* w_coef    = (const float*)d_in[10];
    const float* b_coef    = (const float*)d_in[11];
    const float* w_c1      = (const float*)d_in[12];
    const float* b_c1      = (const float*)d_in[13];
    const float* w_c2      = (const float*)d_in[14];
    const float* b_c2      = (const float*)d_in[15];
    float* out = (float*)d_out;

    static bool attr_done = false;
    if (!attr_done) {
        cudaFuncSetAttribute(prep_kernel,
            cudaFuncAttributeMaxDynamicSharedMemorySize, PP_SMEM * 4);
        cudaFuncSetAttribute(acpredict_kernel,
            cudaFuncAttributeMaxDynamicSharedMemorySize, SM_FLOATS * 4);
        attr_done = true;
    }

    dim3 pblk(64, 8);
    prep_kernel<<<128 + 13, pblk, PP_SMEM * 4>>>(
        post_mean, action, tm11, tm12, tm21, tm22, log_noise,
        w_coef, b_coef, w_c1, b_c1, w_c2, b_c2);

    dim3 blk(32, 30);
    acpredict_kernel<<<128, blk, SM_FLOATS * 4>>>(post_mean, cu, cl, cs, out);
}

// round 4
// speedup vs baseline: 1.7676x; 1.7676x over previous
#include <cuda_runtime.h>
#include <cstdint>

#define NB_B 8192
#define LOD 60
#define LSD 120
#define AD 10
#define NB 15
#define HH 60
#define BX 64
#define BY 12
#define NT 768

typedef unsigned long long u64;

// ---- device scratch ----
__device__ float4 g_tmb[LOD * 7 * NB];     // (t11,t21,t12,t22) banded, k fastest
__device__ float  g_coef[NB * NB_B];       // softmax coefs [k][b]
__device__ float  g_ctlT[NB_B * LSD];      // control, row-major [b][c]
__device__ float  g_tc[LSD];               // elup1(log_noise)

#define FMA2(acc, a, b) asm("fma.rn.f32x2 %0, %1, %2, %0;" : "+l"(acc) : "l"(a), "l"(b))
__device__ __forceinline__ float2 U2F(u64 v){ float2 r; asm("mov.b64 {%0,%1},%2;" : "=f"(r.x), "=f"(r.y) : "l"(v)); return r; }
__device__ __forceinline__ u64 F2U(float x, float y){ u64 r; asm("mov.b64 %0,{%1,%2};" : "=l"(r) : "f"(x), "f"(y)); return r; }
__device__ __forceinline__ u64 LDS64(uint32_t a){ u64 r; asm("ld.shared.b64 %0,[%1];" : "=l"(r) : "r"(a)); return r; }

// ======================= prep kernel =======================
#define PP_PM  0        // 120*66 = 7920 ; reused as ctl stage [120][66]
#define PP_LG  7920     // 15*66
#define PP_ACT 8910     // 10*66
#define PP_H   9570     // 60*66
#define PP_WC  13530    // 1800
#define PP_W1  15330    // 600
#define PP_W2  15930    // 7200
#define PP_B1  23130
#define PP_B2  23190
#define PP_BC  23310
#define PP_SMEM 23328

__global__ void __launch_bounds__(512) prep_kernel(
    const float* __restrict__ post_mean, const float* __restrict__ action,
    const float* __restrict__ tm11, const float* __restrict__ tm12,
    const float* __restrict__ tm21, const float* __restrict__ tm22,
    const float* __restrict__ log_noise,
    const float* __restrict__ w_coef, const float* __restrict__ b_coef,
    const float* __restrict__ w_c1, const float* __restrict__ b_c1,
    const float* __restrict__ w_c2, const float* __restrict__ b_c2)
{
    const int bid = blockIdx.x;
    const int bl = threadIdx.x;          // 0..63
    const int yy = threadIdx.y;          // 0..7
    const int tid = yy * 64 + bl;

    if (bid >= 128) {                    // tmb pack + tc
        if (bid == 128 && tid < LSD) {
            float x = log_noise[tid];
            g_tc[tid] = (x < 0.f) ? expf(x) : x + 1.f;
        }
        int idx = (bid - 128) * 512 + tid;
        if (idx < LOD * 7 * NB) {
            int k = idx % NB;
            int jj = (idx / NB) % 7;
            int i = idx / (NB * 7);
            int j = i + jj - 3;
            float4 v = make_float4(0.f, 0.f, 0.f, 0.f);
            if (j >= 0 && j < LOD) {
                int off = k * LOD * LOD + i * LOD + j;
                v.x = tm11[off]; v.y = tm21[off];
                v.z = tm12[off]; v.w = tm22[off];
            }
            g_tmb[idx] = v;
        }
        return;
    }

    extern __shared__ float sp[];
    const int b0 = bid * 64;

    for (int e = tid; e < 64 * LSD; e += 512) {
        int b = e / LSD, d = e % LSD;
        sp[PP_PM + d * 66 + b] = post_mean[(b0 + b) * LSD + d];
    }
    for (int e = tid; e < 64 * AD; e += 512) {
        int b = e / AD, d = e % AD;
        sp[PP_ACT + d * 66 + b] = action[(b0 + b) * AD + d];
    }
    for (int e = tid; e < NB * LSD; e += 512) sp[PP_WC + e] = w_coef[e];
    for (int e = tid; e < HH * AD; e += 512)  sp[PP_W1 + e] = w_c1[e];
    for (int e = tid; e < LSD * HH; e += 512) sp[PP_W2 + e] = w_c2[e];
    if (tid < HH)  sp[PP_B1 + tid] = b_c1[tid];
    if (tid < LSD) sp[PP_B2 + tid] = b_c2[tid];
    if (tid < NB)  sp[PP_BC + tid] = b_coef[tid];
    __syncthreads();

    // logits
    #pragma unroll
    for (int t = 0; t < 2; t++) {
        int k = yy + 8 * t;
        if (k < NB) {
            float lg = sp[PP_BC + k];
            #pragma unroll 4
            for (int d = 0; d < LSD; d++)
                lg = fmaf(sp[PP_WC + k * LSD + d], sp[PP_PM + d * 66 + bl], lg);
            sp[PP_LG + k * 66 + bl] = lg;
        }
    }
    // hidden layer
    #pragma unroll
    for (int t = 0; t < 8; t++) {
        int i = yy + 8 * t;
        if (i < HH) {
            float hv = sp[PP_B1 + i];
            #pragma unroll
            for (int d = 0; d < AD; d++)
                hv = fmaf(sp[PP_W1 + i * AD + d], sp[PP_ACT + d * 66 + bl], hv);
            sp[PP_H + i * 66 + bl] = fmaxf(hv, 0.f);
        }
    }
    __syncthreads();                     // PM reads done; LG/H ready

    // softmax per batch element
    if (yy == 0) {
        float mx = -1e30f;
        #pragma unroll
        for (int k = 0; k < NB; k++) mx = fmaxf(mx, sp[PP_LG + k * 66 + bl]);
        float ex[NB], sum = 0.f;
        #pragma unroll
        for (int k = 0; k < NB; k++) {
            ex[k] = expf(sp[PP_LG + k * 66 + bl] - mx);
            sum += ex[k];
        }
        float inv = 1.f / sum;
        #pragma unroll
        for (int k = 0; k < NB; k++)
            g_coef[k * NB_B + b0 + bl] = ex[k] * inv;
    }
    // control output -> stage in PM region (PM is dead now)
    #pragma unroll
    for (int t = 0; t < 15; t++) {
        int c = yy + 8 * t;
        float ctl = sp[PP_B2 + c];
        #pragma unroll 4
        for (int m = 0; m < HH; m++)
            ctl = fmaf(sp[PP_W2 + c * HH + m], sp[PP_H + m * 66 + bl], ctl);
        sp[PP_PM + c * 66 + bl] = ctl;
    }
    __syncthreads();

    // coalesced transposed store of control
    for (int e = tid; e < 64 * LSD; e += 512) {
        int b = e / LSD, c = e % LSD;
        g_ctlT[(b0 + b) * LSD + c] = sp[PP_PM + c * 66 + b];
    }
}

// ======================= main kernel =======================
// smem float offsets
#define SM_TMB   0        // 25200 floats (float4[6300]); reused as stage[300*67]
#define SM_MUML  25200    // float2[60][66] -> 7920 floats
#define SM_CUCL  33120    // 7920
#define SM_CS2   41040    // 3960
#define SM_COEF  45000    // u64[15][64] -> 1920 floats
#define SM_TC    46920    // 120
#define SM_FLOATS 47040   // 188160 bytes

template<int J0, int JN>
__device__ __forceinline__ void mix_pass(
    uint32_t tmbRow, uint32_t coefA, u64* aX, u64* aY)
{
    #pragma unroll
    for (int jj = 0; jj < JN; jj++) { aX[jj] = 0; aY[jj] = 0; }
    #pragma unroll
    for (int k = 0; k < NB; k++) {
        u64 c2 = LDS64(coefA + (uint32_t)(k * 512));
        #pragma unroll
        for (int jj = 0; jj < JN; jj++) {
            u64 vX, vY;   // (t11,t21), (t12,t22) — warp-uniform broadcast
            asm("ld.shared.v2.u64 {%0,%1},[%2];"
                : "=l"(vX), "=l"(vY)
                : "r"(tmbRow + (uint32_t)(((J0 + jj) * NB + k) * 16)));
            FMA2(aX[jj], c2, vX);
            FMA2(aY[jj], c2, vY);
        }
    }
}

__device__ __forceinline__ void combine(
    u64 aXv, u64 aYv, bool diag, int jc, int x, const float* __restrict__ sm,
    float& nmu, float& nml, float& ncu, float& ncl, float& ncs)
{
    float2 X = U2F(aXv), Y = U2F(aYv);
    float t11 = X.x, t21 = X.y, t12 = Y.x, t22 = Y.y;
    if (diag) { t11 += 1.f; t22 += 1.f; }
    float2 mm = ((const float2*)(sm + SM_MUML))[jc * 66 + x];   // (mu, ml)
    float2 cc = ((const float2*)(sm + SM_CUCL))[jc * 66 + x];   // (cu, cl)
    float cs2 = sm[SM_CS2 + jc * 66 + x];
    nmu = fmaf(t11, mm.x, fmaf(t12, mm.y, nmu));
    nml = fmaf(t21, mm.x, fmaf(t22, mm.y, nml));
    ncu = fmaf(t11 * t11, cc.x, fmaf(t11 * t12, cs2, fmaf(t12 * t12, cc.y, ncu)));
    ncl = fmaf(t21 * t21, cc.x, fmaf(t21 * t22, cs2, fmaf(t22 * t22, cc.y, ncl)));
    ncs = fmaf(t21 * t11, cc.x,
          fmaf(0.5f * fmaf(t22, t11, t21 * t12), cs2,
          fmaf(t22 * t12, cc.y, ncs)));
}

__global__ void __launch_bounds__(NT, 1) acpredict_kernel(
    const float* __restrict__ post_mean, const float* __restrict__ cu_g,
    const float* __restrict__ cl_g, const float* __restrict__ cs_g,
    float* __restrict__ out)
{
    extern __shared__ float sm[];
    const int x   = threadIdx.x;           // 0..63 : batch element
    const int y   = threadIdx.y;           // 0..11 : row group
    const int tid = y * BX + x;
    const int b0  = blockIdx.x * BX;

    // ---- loads ----
    {
        float4* t4 = (float4*)sm;
        for (int e = tid; e < LOD * 7 * NB; e += NT) t4[e] = g_tmb[e];
    }
    for (int e = tid; e < BX * LSD; e += NT) {
        int bl = e / LSD, d = e % LSD;
        float v = post_mean[(b0 + bl) * LSD + d];
        int j = (d < LOD) ? d : d - LOD;
        sm[SM_MUML + (j * 66 + bl) * 2 + (d < LOD ? 0 : 1)] = v;
    }
    for (int e = tid; e < BX * LOD; e += NT) {
        int bl = e / LOD, j = e % LOD;
        sm[SM_CUCL + (j * 66 + bl) * 2 + 0] = cu_g[(b0 + bl) * LOD + j];
        sm[SM_CUCL + (j * 66 + bl) * 2 + 1] = cl_g[(b0 + bl) * LOD + j];
        sm[SM_CS2 + j * 66 + bl] = 2.f * cs_g[(b0 + bl) * LOD + j];
    }
    for (int e = tid; e < NB * BX; e += NT) {
        int k = e / BX, bl = e % BX;
        float c = g_coef[k * NB_B + b0 + bl];
        ((u64*)(sm + SM_COEF))[k * BX + bl] = F2U(c, c);
    }
    if (tid < LSD) sm[SM_TC + tid] = g_tc[tid];
    __syncthreads();

    const uint32_t sbase = (uint32_t)__cvta_generic_to_shared(sm);
    const uint32_t coefA = sbase + SM_COEF * 4 + (uint32_t)x * 8u;

    float res[5][5];

    #pragma unroll
    for (int t = 0; t < 5; t++) {
        const int i = y + BY * t;
        const uint32_t tmbRow = sbase + (uint32_t)(i * 7 * NB * 16);
        float nmu = 0.f, nml = 0.f, ncu = 0.f, ncl = 0.f, ncs = 0.f;
        {   // jj 0..3
            u64 aX[4], aY[4];
            mix_pass<0, 4>(tmbRow, coefA, aX, aY);
            #pragma unroll
            for (int jj = 0; jj < 4; jj++) {
                int jc = max(i + jj - 3, 0);
                combine(aX[jj], aY[jj], jj == 3, jc, x, sm, nmu, nml, ncu, ncl, ncs);
            }
        }
        {   // jj 4..6
            u64 aX[3], aY[3];
            mix_pass<4, 3>(tmbRow, coefA, aX, aY);
            #pragma unroll
            for (int jj = 0; jj < 3; jj++) {
                int jc = min(i + 1 + jj, LOD - 1);
                combine(aX[jj], aY[jj], false, jc, x, sm, nmu, nml, ncu, ncl, ncs);
            }
        }
        res[t][0] = nmu; res[t][1] = nml;
        res[t][2] = ncu; res[t][3] = ncl; res[t][4] = ncs;
    }

    __syncthreads();                 // all tmb/input reads complete
    #pragma unroll
    for (int t = 0; t < 5; t++) {    // stage into dead tmb region, stride 67
        int i = y + BY * t;
        sm[(i)        * 67 + x] = res[t][0];
        sm[(LOD + i)  * 67 + x] = res[t][1];
        sm[(120 + i)  * 67 + x] = res[t][2];
        sm[(180 + i)  * 67 + x] = res[t][3];
        sm[(240 + i)  * 67 + x] = res[t][4];
    }
    __syncthreads();

    // ---- coalesced stores; fold in control + trans_cov here ----
    for (int e = tid; e < BX * 300; e += NT) {
        int bl = e / 300, c = e % 300;
        float v = sm[c * 67 + bl];
        int bb = b0 + bl;
        if (c < 120) {
            v += __ldg(&g_ctlT[bb * LSD + c]);
            out[bb * 120 + c] = v;
        } else {
            if (c < 240) v += sm[SM_TC + (c - 120)];
            int blk = c / 60;        // 2, 3, 4
            out[NB_B * 60 * blk + bb * 60 + (c - blk * 60)] = v;
        }
    }
}

extern "C" void kernel_launch(void* const* d_in, const int* in_sizes, int n_in,
                              void* d_out, int out_size) {
    const float* post_mean = (const float*)d_in[0];
    const float* cu        = (const float*)d_in[1];
    const float* cl        = (const float*)d_in[2];
    const float* cs        = (const float*)d_in[3];
    const float* action    = (const float*)d_in[4];
    const float* tm11      = (const float*)d_in[5];
    const float* tm12      = (const float*)d_in[6];
    const float* tm21      = (const float*)d_in[7];
    const float* tm22      = (const float*)d_in[8];
    const float* log_noise = (const float*)d_in[9];
    const float* w_coef    = (const float*)d_in[10];
    const float* b_coef    = (const float*)d_in[11];
    const float* w_c1      = (const float*)d_in[12];
    const float* b_c1      = (const float*)d_in[13];
    const float* w_c2      = (const float*)d_in[14];
    const float* b_c2      = (const float*)d_in[15];
    float* out = (float*)d_out;

    static bool attr_done = false;
    if (!attr_done) {
        cudaFuncSetAttribute(prep_kernel,
            cudaFuncAttributeMaxDynamicSharedMemorySize, PP_SMEM * 4);
        cudaFuncSetAttribute(acpredict_kernel,
            cudaFuncAttributeMaxDynamicSharedMemorySize, SM_FLOATS * 4);
        attr_done = true;
    }

    dim3 pblk(64, 8);
    prep_kernel<<<128 + 13, pblk, PP_SMEM * 4>>>(
        post_mean, action, tm11, tm12, tm21, tm22, log_noise,
        w_coef, b_coef, w_c1, b_c1, w_c2, b_c2);

    dim3 blk(BX, BY);
    acpredict_kernel<<<NB_B / BX, blk, SM_FLOATS * 4>>>(post_mean, cu, cl, cs, out);
}